// round 5
// baseline (speedup 1.0000x reference)
#include <cuda_runtime.h>
#include <math.h>

// ---------------- problem constants ----------------
#define NYI   300
#define NXI   300
#define PML_W 20
#define NYP   340
#define NXP   340
#define NT    128
#define NSHOT 2
#define NREC  32
#define DT_F    0.001f
#define INV_DX  0.2f
#define C1F     1.125f
#define C2F     (-1.0f/24.0f)

// ---------------- tiling ----------------
#define TS    8
#define TILE  43
#define NB    (NSHOT*TS*TS)           // 128 CTAs
#define NTHR  512
#define SP    53                      // smem row pitch (tile + 8 halo + pad, odd)
#define SROWS 51                      // tile + 8 halo rows
#define FSZ   (SROWS*SP)              // 2703
#define NFS   17                      // 13 state + 4 material fields
#define SMEM_BYTES ((NFS*FSZ + 128)*4)   // 184316 B

enum {F_VY=0,F_VX,F_SYY,F_SXX,F_SXY,F_MVYY,F_MVYX,F_MVXY,F_MVXX,
      F_MSYYY,F_MSXYX,F_MSXYY,F_MSXXX,F_BUO,F_LAM,F_LP2M,F_MU};

// ---------------- exchange: 3 stress fields, 4-wide strips + 4x4 corners, double buffered ----
#define XFS   752                     // per field: 4 sides*4*43 + 4 corners*16
#define XCTA  (3*XFS)                 // 2256 floats per CTA
__device__ float g_xch[2][NB*XCTA];
__device__ int   g_flag[NB];

__global__ void k_init(){ if (threadIdx.x < NB) g_flag[threadIdx.x] = 0; }

__device__ __forceinline__ float pml_b(int u)
{
    double d0 = 414.4653366865718;    // 3*2000/(2*20*5)*ln(1e6)
    double lo = (20.0 - (double)u) / 20.0; lo = lo < 0.0 ? 0.0 : (lo > 1.0 ? 1.0 : lo);
    double hi = ((double)u - 319.0) / 20.0; hi = hi < 0.0 ? 0.0 : (hi > 1.0 ? 1.0 : hi);
    double mm = lo > hi ? lo : hi;
    return (float)exp(-d0 * mm * mm * 0.001);
}

// ---------------- per-cell physics (all operands in SMEM) ----------------
__device__ __forceinline__ void cellV(int o, float byk, float bxk,
    int srcoff, float srcamp,
    float* SVY, float* SVX, const float* SSYY, const float* SSXX, const float* SSXY,
    float* SMSYYY, float* SMSXYX, float* SMSXYY, float* SMSXXX, const float* SBUO)
{
    float d, m, t1, t2;
    d = (C1F*(SSYY[o+SP]-SSYY[o]) + C2F*(SSYY[o+2*SP]-SSYY[o-SP]))*INV_DX;
    t1 = d;
    if (byk != 1.0f){ m = SMSYYY[o]; m = byk*m + (byk-1.0f)*d; SMSYYY[o] = m; t1 += m; }
    d = (C1F*(SSXY[o]-SSXY[o-1]) + C2F*(SSXY[o+1]-SSXY[o-2]))*INV_DX;
    t2 = d;
    if (bxk != 1.0f){ m = SMSXYX[o]; m = bxk*m + (bxk-1.0f)*d; SMSXYX[o] = m; t2 += m; }
    float buo = SBUO[o];
    float nvy = SVY[o] + DT_F*buo*(t1 + t2);
    if (o == srcoff) nvy += srcamp;
    SVY[o] = nvy;
    d = (C1F*(SSXY[o]-SSXY[o-SP]) + C2F*(SSXY[o+SP]-SSXY[o-2*SP]))*INV_DX;
    t1 = d;
    if (byk != 1.0f){ m = SMSXYY[o]; m = byk*m + (byk-1.0f)*d; SMSXYY[o] = m; t1 += m; }
    d = (C1F*(SSXX[o+1]-SSXX[o]) + C2F*(SSXX[o+2]-SSXX[o-1]))*INV_DX;
    t2 = d;
    if (bxk != 1.0f){ m = SMSXXX[o]; m = bxk*m + (bxk-1.0f)*d; SMSXXX[o] = m; t2 += m; }
    SVX[o] += DT_F*buo*(t1 + t2);
}

__device__ __forceinline__ void cellS(int o, float byk, float bxk,
    const float* SVY, const float* SVX, float* SSYY, float* SSXX, float* SSXY,
    float* SMVYY, float* SMVYX, float* SMVXY, float* SMVXX,
    const float* SLAM, const float* SLP2M, const float* SMU)
{
    float d, m;
    d = (C1F*(SVY[o]-SVY[o-SP]) + C2F*(SVY[o+SP]-SVY[o-2*SP]))*INV_DX;
    float dyy = d;
    if (byk != 1.0f){ m = SMVYY[o]; m = byk*m + (byk-1.0f)*d; SMVYY[o] = m; dyy += m; }
    d = (C1F*(SVX[o]-SVX[o-1]) + C2F*(SVX[o+1]-SVX[o-2]))*INV_DX;
    float dxx = d;
    if (bxk != 1.0f){ m = SMVXX[o]; m = bxk*m + (bxk-1.0f)*d; SMVXX[o] = m; dxx += m; }
    float lam = SLAM[o], lp2m = SLP2M[o];
    SSYY[o] += DT_F*(lp2m*dyy + lam*dxx);
    SSXX[o] += DT_F*(lp2m*dxx + lam*dyy);
    d = (C1F*(SVY[o+1]-SVY[o]) + C2F*(SVY[o+2]-SVY[o-1]))*INV_DX;
    float dyx = d;
    if (bxk != 1.0f){ m = SMVYX[o]; m = bxk*m + (bxk-1.0f)*d; SMVYX[o] = m; dyx += m; }
    d = (C1F*(SVX[o+SP]-SVX[o]) + C2F*(SVX[o+2*SP]-SVX[o-SP]))*INV_DX;
    float dxy = d;
    if (byk != 1.0f){ m = SMVXY[o]; m = byk*m + (byk-1.0f)*d; SMVXY[o] = m; dxy += m; }
    SSXY[o] += DT_F*SMU[o]*(dyx + dxy);
}

// ---------------- stress exchange: write my strips/corners ----------------
__device__ __forceinline__ void xchg_write(const float* SSYY, const float* SSXX, const float* SSXY,
                                           float* buf, int me, int th, int tw, int tid)
{
    for (int i = tid; i < XCTA; i += NTHR){
        int f = i / XFS; int r = i - f*XFS;
        int lr, lc;
        if (r < 688){
            int side = r / 172; int e = r - side*172;
            if (side < 2){ int row4 = e/43; int col = e - row4*43;
                lr = (side == 0) ? 4+row4 : th+row4;  lc = 4+col; }
            else { int col4 = e/43; int row = e - col4*43;
                lr = 4+row;  lc = (side == 2) ? 4+col4 : tw+col4; }
        } else {
            int r2 = r - 688; int c = r2 >> 4; int e = r2 & 15;
            int rr = e >> 2, cc = e & 3;
            lr = (c >= 2) ? th+rr : 4+rr;
            lc = (c & 1)  ? tw+cc : 4+cc;
        }
        const float* F = (f == 0) ? SSYY : ((f == 1) ? SSXX : SSXY);
        buf[me*XCTA + i] = F[lr*SP + lc];
    }
}

// ---------------- stress exchange: read neighbor strips/corners into my halos ----------------
__device__ __forceinline__ void xchg_read(float* SSYY, float* SSXX, float* SSXY,
                                          const float* buf, int me, int th, int tw,
                                          bool hN, bool hS, bool hW, bool hE, int tid)
{
    for (int i = tid; i < XCTA; i += NTHR){
        int f = i / XFS; int r = i - f*XFS;
        int src_cta, src_i, lr, lc; bool ok;
        if (r < 688){
            int side = r / 172; int e = r - side*172;
            if (side == 0){ ok = hN; src_cta = me-TS; src_i = f*XFS + 1*172 + e;
                int row4 = e/43, col = e - row4*43; lr = row4;      lc = 4+col; }
            else if (side == 1){ ok = hS; src_cta = me+TS; src_i = f*XFS + 0*172 + e;
                int row4 = e/43, col = e - row4*43; lr = 4+th+row4; lc = 4+col; }
            else if (side == 2){ ok = hW; src_cta = me-1; src_i = f*XFS + 3*172 + e;
                int col4 = e/43, row = e - col4*43; lr = 4+row;     lc = col4; }
            else { ok = hE; src_cta = me+1; src_i = f*XFS + 2*172 + e;
                int col4 = e/43, row = e - col4*43; lr = 4+row;     lc = 4+tw+col4; }
        } else {
            int r2 = r - 688; int c = r2 >> 4; int e = r2 & 15;
            int rr = e >> 2, cc = e & 3; int nc;
            if (c == 0){ ok = hN && hW; src_cta = me-TS-1; nc = 3; lr = rr;      lc = cc; }
            else if (c == 1){ ok = hN && hE; src_cta = me-TS+1; nc = 2; lr = rr; lc = 4+tw+cc; }
            else if (c == 2){ ok = hS && hW; src_cta = me+TS-1; nc = 1; lr = 4+th+rr; lc = cc; }
            else { ok = hS && hE; src_cta = me+TS+1; nc = 0; lr = 4+th+rr; lc = 4+tw+cc; }
            src_i = f*XFS + 688 + nc*16 + e;
        }
        if (ok){
            float v = __ldcg(&buf[src_cta*XCTA + src_i]);
            float* F = (f == 0) ? SSYY : ((f == 1) ? SSXX : SSXY);
            F[lr*SP + lc] = v;
        }
    }
}

__global__ void __launch_bounds__(NTHR, 1)
k_main(const float* __restrict__ lamb,
       const float* __restrict__ muv,
       const float* __restrict__ buov,
       const float* __restrict__ amp,    // [NSHOT,1,NT]
       const int*   __restrict__ sloc,   // [NSHOT,1,2]
       const int*   __restrict__ rloc,   // [NSHOT,NREC,2]
       float*       __restrict__ out)    // [NSHOT,NREC,NT]
{
    extern __shared__ float sm[];
    const int tid  = threadIdx.x;
    const int me   = blockIdx.x;
    const int shot = me >> 6;
    const int tile = me & 63;
    const int ty   = tile >> 3, tx = tile & 7;
    const int y0   = ty * TILE, x0 = tx * TILE;
    const int th   = (y0 + TILE <= NYP) ? TILE : (NYP - y0);
    const int tw   = (x0 + TILE <= NXP) ? TILE : (NXP - x0);
    const bool hN = (ty > 0), hS = (ty < TS-1), hW = (tx > 0), hE = (tx < TS-1);

    float* SVY    = sm + F_VY   *FSZ;
    float* SVX    = sm + F_VX   *FSZ;
    float* SSYY   = sm + F_SYY  *FSZ;
    float* SSXX   = sm + F_SXX  *FSZ;
    float* SSXY   = sm + F_SXY  *FSZ;
    float* SMVYY  = sm + F_MVYY *FSZ;
    float* SMVYX  = sm + F_MVYX *FSZ;
    float* SMVXY  = sm + F_MVXY *FSZ;
    float* SMVXX  = sm + F_MVXX *FSZ;
    float* SMSYYY = sm + F_MSYYY*FSZ;
    float* SMSXYX = sm + F_MSXYX*FSZ;
    float* SMSXYY = sm + F_MSXYY*FSZ;
    float* SMSXXX = sm + F_MSXXX*FSZ;
    float* SBUO   = sm + F_BUO  *FSZ;
    float* SLAM   = sm + F_LAM  *FSZ;
    float* SLP2M  = sm + F_LP2M *FSZ;
    float* SMU    = sm + F_MU   *FSZ;

    // zero all 13 state fields (incl. halos)
    for (int i = tid; i < 13*FSZ; i += NTHR) sm[i] = 0.0f;

    // fill materials (clamped model replication into PML/halo)
    for (int i = tid; i < FSZ; i += NTHR){
        int lr = i / SP, lc = i - lr*SP;
        int gy = y0 - 4 + lr, gx = x0 - 4 + lc;
        int iy = gy - PML_W; iy = iy < 0 ? 0 : (iy > NYI-1 ? NYI-1 : iy);
        int ix = gx - PML_W; ix = ix < 0 ? 0 : (ix > NXI-1 ? NXI-1 : ix);
        float l = lamb[iy*NXI + ix];
        float m = muv [iy*NXI + ix];
        SBUO[i]  = buov[iy*NXI + ix];
        SLAM[i]  = l;
        SLP2M[i] = l + 2.0f*m;
        SMU[i]   = m;
    }

    // ---- V region: tile extended by 2 (clipped to domain) ----
    const int vy0g = (y0-2 < 0) ? 0 : y0-2;
    const int vy1g = (y0+th+2 > NYP) ? NYP : y0+th+2;
    const int vx0g = (x0-2 < 0) ? 0 : x0-2;
    const int vx1g = (x0+tw+2 > NXP) ? NXP : x0+tw+2;
    const int vh = vy1g - vy0g, vw = vx1g - vx0g;
    const int vlr0 = vy0g - (y0-4), vlc0 = vx0g - (x0-4);

    int vo[5]; float vby[5], vbx[5];
#pragma unroll
    for (int k = 0; k < 5; k++){
        int idx = tid + k*NTHR;
        if (idx < vh*vw){
            int li = idx / vw, lj = idx - li*vw;
            vo[k]  = (vlr0+li)*SP + (vlc0+lj);
            vby[k] = pml_b(vy0g + li);
            vbx[k] = pml_b(vx0g + lj);
        } else { vo[k] = -1; vby[k] = 1.0f; vbx[k] = 1.0f; }
    }

    // source local offset (in V-region coords) or -2
    const int sy = sloc[shot*2 + 0] + PML_W;
    const int sx = sloc[shot*2 + 1] + PML_W;
    int srcoff = -2;
    if (sy >= vy0g && sy < vy1g && sx >= vx0g && sx < vx1g)
        srcoff = (sy - (y0-4))*SP + (sx - (x0-4));

    // ---- S frame cells (outer 4-wide ring of the tile, <=2/thread) ----
    const int nframe = th*tw - (th-8)*(tw-8);
    int fo[2]; float fby[2], fbx[2];
#pragma unroll
    for (int k = 0; k < 2; k++){
        int idx = tid + k*NTHR;
        if (idx < nframe){
            int li, lj;
            if (idx < 4*tw){ li = idx / tw; lj = idx - li*tw; }
            else if (idx < 8*tw){ int q = idx / tw; li = th - 8 + q; lj = idx - q*tw; }
            else { int q = idx - 8*tw; li = 4 + (q >> 3); int w = q & 7;
                   lj = (w < 4) ? w : tw - 8 + w; }
            fo[k]  = (4+li)*SP + (4+lj);
            fby[k] = pml_b(y0 + li);
            fbx[k] = pml_b(x0 + lj);
        } else { fo[k] = -1; fby[k] = 1.0f; fbx[k] = 1.0f; }
    }

    // ---- S interior cells (<=3/thread) ----
    const int iw = tw - 8;
    const int nint = (th-8)*iw;
    int io[3]; float iby[3], ibx[3];
#pragma unroll
    for (int k = 0; k < 3; k++){
        int idx = tid + k*NTHR;
        if (idx < nint){
            int li = 4 + idx / iw, lj = 4 + (idx - (idx/iw)*iw);
            io[k]  = (4+li)*SP + (4+lj);
            iby[k] = pml_b(y0 + li);
            ibx[k] = pml_b(x0 + lj);
        } else { io[k] = -1; iby[k] = 1.0f; ibx[k] = 1.0f; }
    }

    // receiver ownership
    int rsoff = -1, rout = -1;
    if (tid < NSHOT*NREC){
        int rs = tid >> 5;
        int ry = rloc[tid*2 + 0] + PML_W;
        int rx = rloc[tid*2 + 1] + PML_W;
        if (rs == shot && ry >= y0 && ry < y0+th && rx >= x0 && rx < x0+tw){
            rsoff = (ry - y0 + 4)*SP + (rx - x0 + 4);
            rout  = tid*NT;
        }
    }
    __syncthreads();

    for (int t = 0; t < NT; t++){
        const float srcamp = amp[shot*NT + t];
        float* buf = g_xch[t & 1];

        // ===== V phase on tile+2 (stress halos fresh from last exchange) =====
#pragma unroll
        for (int k = 0; k < 5; k++) if (vo[k] >= 0)
            cellV(vo[k], vby[k], vbx[k], srcoff, srcamp,
                  SVY, SVX, SSYY, SSXX, SSXY, SMSYYY, SMSXYX, SMSXYY, SMSXXX, SBUO);
        __syncthreads();

        if (rout >= 0) out[rout + t] = SVY[rsoff];

        // ===== S phase: frame first =====
#pragma unroll
        for (int k = 0; k < 2; k++) if (fo[k] >= 0)
            cellS(fo[k], fby[k], fbx[k], SVY, SVX, SSYY, SSXX, SSXY,
                  SMVYY, SMVYX, SMVXY, SMVXX, SLAM, SLP2M, SMU);
        __syncthreads();

        // export stress strips + corners, publish epoch t+1
        xchg_write(SSYY, SSXX, SSXY, buf, me, th, tw, tid);
        __syncthreads();
        if (tid == 0){ __threadfence(); atomicExch(&g_flag[me], t + 1); }

        // ===== S interior (overlaps neighbor publish latency) =====
#pragma unroll
        for (int k = 0; k < 3; k++) if (io[k] >= 0)
            cellS(io[k], iby[k], ibx[k], SVY, SVX, SSYY, SSXX, SSXY,
                  SMVYY, SMVYX, SMVXY, SMVXX, SLAM, SLP2M, SMU);

        // wait for all 8 neighbors, acquire
        {
            const int e = t + 1;
            if (tid == 32  && hN){ volatile int* f = &g_flag[me-TS];   while (*f < e) {} __threadfence(); }
            if (tid == 64  && hS){ volatile int* f = &g_flag[me+TS];   while (*f < e) {} __threadfence(); }
            if (tid == 96  && hW){ volatile int* f = &g_flag[me-1 ];   while (*f < e) {} __threadfence(); }
            if (tid == 128 && hE){ volatile int* f = &g_flag[me+1 ];   while (*f < e) {} __threadfence(); }
            if (tid == 160 && hN && hW){ volatile int* f = &g_flag[me-TS-1]; while (*f < e) {} __threadfence(); }
            if (tid == 192 && hN && hE){ volatile int* f = &g_flag[me-TS+1]; while (*f < e) {} __threadfence(); }
            if (tid == 224 && hS && hW){ volatile int* f = &g_flag[me+TS-1]; while (*f < e) {} __threadfence(); }
            if (tid == 256 && hS && hE){ volatile int* f = &g_flag[me+TS+1]; while (*f < e) {} __threadfence(); }
        }
        __syncthreads();

        // import neighbor stress halos
        xchg_read(SSYY, SSXX, SSXY, buf, me, th, tw, hN, hS, hW, hE, tid);
        __syncthreads();
    }
}

// ---------------- launch ----------------
extern "C" void kernel_launch(void* const* d_in, const int* in_sizes, int n_in,
                              void* d_out, int out_size)
{
    const float* lamb = (const float*)d_in[0];
    const float* mu   = (const float*)d_in[1];
    const float* buo  = (const float*)d_in[2];
    const float* amp  = (const float*)d_in[3];
    const int*   sloc = (const int*)  d_in[4];
    const int*   rloc = (const int*)  d_in[5];
    float* out = (float*)d_out;

    static bool attr_set = false;
    if (!attr_set){
        cudaFuncSetAttribute(k_main, cudaFuncAttributeMaxDynamicSharedMemorySize, SMEM_BYTES);
        attr_set = true;
    }

    k_init<<<1, 128>>>();
    k_main<<<NB, NTHR, SMEM_BYTES>>>(lamb, mu, buo, amp, sloc, rloc, out);
}